// round 10
// baseline (speedup 1.0000x reference)
#include <cuda_runtime.h>
#include <cuda_bf16.h>
#include <math.h>
#include <stdint.h>

#define NTOK 16384
#define HID  1024
#define FFN  4096
#define NE   8
#define NROWS (NTOK * 2)
#define NROWSP (NROWS + NE * 128)     // padded rows upper bound = 33792
#define MAXTILES (NROWSP / 128)       // 264

// ---------------- device scratch ----------------
__device__ int   g_cnt[NE];
__device__ int   g_cur[NE];
__device__ int   g_po[NE + 1];
__device__ int   g_ntiles;
__device__ int   g_bad1;
__device__ int   g_bad2;
__device__ int   g_tile_e[MAXTILES];
__device__ int   g_topk_e[NROWS];
__device__ float g_topk_w[NROWS];
__device__ int   g_rowtok[NROWSP];
__device__ int   g_prow[NROWS];
__device__ float g_xg[(size_t)NROWSP * HID];
__device__ float g_h[(size_t)NROWSP * FFN];
__device__ float g_y[(size_t)NROWSP * HID];

// ---------------- helpers ----------------
__device__ __forceinline__ float rn_tf32(float v) {
    float o;
    asm("cvt.rna.tf32.f32 %0, %1;" : "=f"(o) : "f"(v));
    return o;
}

#define CP_ASYNC16(dst, src) \
    asm volatile("cp.async.cg.shared.global [%0], [%1], 16;" :: "r"(dst), "l"(src))
#define CP_COMMIT() asm volatile("cp.async.commit_group;" ::: "memory")
#define CP_WAIT(n)  asm volatile("cp.async.wait_group %0;" :: "n"(n) : "memory")

__device__ __forceinline__ void mma_tf32(float& c0, float& c1, float& c2, float& c3,
                                         uint32_t a0, uint32_t a1, uint32_t a2, uint32_t a3,
                                         uint32_t b0, uint32_t b1) {
    asm volatile(
        "mma.sync.aligned.m16n8k8.row.col.f32.tf32.tf32.f32 "
        "{%0,%1,%2,%3}, {%4,%5,%6,%7}, {%8,%9}, {%0,%1,%2,%3};"
        : "+f"(c0), "+f"(c1), "+f"(c2), "+f"(c3)
        : "r"(a0), "r"(a1), "r"(a2), "r"(a3), "r"(b0), "r"(b1));
}

// ---------------- gating ----------------
__global__ __launch_bounds__(256) void zero_kernel() {
    int t = threadIdx.x;
    if (t < NE) { g_cnt[t] = 0; g_cur[t] = 0; }
    if (t == 8) g_bad1 = 0;
    if (t == 9) g_bad2 = 0;
}

__global__ __launch_bounds__(256) void gate_kernel(const float* __restrict__ x,
                                                   const float* __restrict__ Wg,
                                                   const float* __restrict__ bg) {
    int warp = (blockIdx.x * blockDim.x + threadIdx.x) >> 5;
    int lane = threadIdx.x & 31;
    if (warp >= NTOK) return;
    const float* xr = x + (size_t)warp * HID;
    float acc[NE];
    #pragma unroll
    for (int e = 0; e < NE; e++) acc[e] = 0.f;
    for (int i = lane; i < HID; i += 32) {
        float xi = xr[i];
        #pragma unroll
        for (int e = 0; e < NE; e++) acc[e] += xi * Wg[i * NE + e];
    }
    #pragma unroll
    for (int o = 16; o; o >>= 1) {
        #pragma unroll
        for (int e = 0; e < NE; e++) acc[e] += __shfl_xor_sync(0xFFFFFFFFu, acc[e], o);
    }
    if (lane == 0) {
        float s[NE];
        #pragma unroll
        for (int e = 0; e < NE; e++) s[e] = acc[e] + bg[e];
        int i0 = 0;
        #pragma unroll
        for (int e = 1; e < NE; e++) if (s[e] > s[i0]) i0 = e;
        int i1 = -1;
        #pragma unroll
        for (int e = 0; e < NE; e++) {
            if (e == i0) continue;
            if (i1 < 0 || s[e] > s[i1]) i1 = e;
        }
        float e1 = expf(s[i1] - s[i0]);
        float denom = 1.f + e1;
        g_topk_e[warp * 2]     = i0;  g_topk_w[warp * 2]     = 1.f / denom;
        g_topk_e[warp * 2 + 1] = i1;  g_topk_w[warp * 2 + 1] = e1 / denom;
        atomicAdd(&g_cnt[i0], 1);
        atomicAdd(&g_cnt[i1], 1);
    }
}

// scan + pad-fill in one block
__global__ __launch_bounds__(256) void scanpad_kernel() {
    if (threadIdx.x == 0) {
        int acc = 0, t = 0;
        for (int e = 0; e < NE; e++) {
            g_po[e] = acc;
            int nt = (g_cnt[e] + 127) >> 7;
            for (int i = 0; i < nt; i++) g_tile_e[t++] = e;
            acc += nt << 7;
        }
        g_po[NE] = acc;
        g_ntiles = t;
    }
    __syncthreads();
    for (int e = 0; e < NE; e++) {
        int base = g_po[e];
        int padded = g_po[e + 1] - base;
        for (int r = g_cnt[e] + threadIdx.x; r < padded; r += 256)
            g_rowtok[base + r] = 0;
    }
}

__global__ __launch_bounds__(256) void assign_kernel() {
    int t = blockIdx.x * blockDim.x + threadIdx.x;
    if (t >= NTOK) return;
    #pragma unroll
    for (int k = 0; k < 2; k++) {
        int e = g_topk_e[t * 2 + k];
        int p = g_po[e] + atomicAdd(&g_cur[e], 1);
        g_rowtok[p] = t;
        g_prow[t * 2 + k] = p;
    }
}

// gather x rows (RN-rounded to tf32) into padded g_xg
__global__ __launch_bounds__(256) void gather_kernel(const float* __restrict__ x) {
    int row = blockIdx.x;
    if (row >= g_po[NE]) return;
    int tok = g_rowtok[row];
    const float4* s = (const float4*)(x + (size_t)tok * HID);
    float4* d = (float4*)(g_xg + (size_t)row * HID);
    float4 v = s[threadIdx.x];
    v.x = rn_tf32(v.x); v.y = rn_tf32(v.y); v.z = rn_tf32(v.z); v.w = rn_tf32(v.w);
    d[threadIdx.x] = v;
}

// ---------------- tf32 mma GEMM: 128x256x32, 512 thr, 4-stage cp.async ----------------
// A smem: [128 m][36 k-stride].  B smem: [32 k][264 n-stride], native W rows.
#define BK 32
#define KSTR 36
#define BSTR 264
#define A_FLOATS (128 * KSTR)              // 4608
#define B_FLOATS (BK * BSTR)               // 8448
#define STAGE_FLOATS (A_FLOATS + B_FLOATS) // 13056
#define STAGE_BYTES (STAGE_FLOATS * 4)
#define NSTG 4
#define MM_SMEM (NSTG * STAGE_BYTES)       // 208896 bytes

template<int KD, int ND, bool FIRST>
__global__ __launch_bounds__(512, 1) void mma_gemm(const float* __restrict__ W,
                                                   const float* __restrict__ bias_all) {
    int tile = blockIdx.y;
    if (tile >= g_ntiles) return;
    const float* Amat = FIRST ? g_xg : g_h;
    float*       Omat = FIRST ? g_h  : g_y;
    int e  = g_tile_e[tile];
    int n0 = blockIdx.x * 256;
    size_t m0 = (size_t)tile * 128;
    const float* Ab = Amat + m0 * KD;
    const float* Wb = W + (size_t)e * KD * ND + n0;     // [k][n] rows
    const float* biasb = bias_all + (size_t)e * ND + n0;

    extern __shared__ float smem[];
    uint32_t smem_b = (uint32_t)__cvta_generic_to_shared(smem);

    int t = threadIdx.x;
    int wid = t >> 5, lane = t & 31;
    int wm = wid & 1, wn = wid >> 1;        // warp tile (wm*64 rows, wn*32 cols)
    int qr = lane >> 2, qc = lane & 3;

    // copy bases (chunk j offsets are compile-time constants)
    const float* srcA = Ab + (size_t)(t >> 3) * KD + (t & 7) * 4;                 // j=1: +64*KD
    uint32_t dstA = smem_b + (uint32_t)((t >> 3) * KSTR + (t & 7) * 4) * 4;       // j=1: +64*KSTR*4
    const float* srcB = Wb + (size_t)(t >> 6) * ND + (t & 63) * 4;                // j: +j*8*ND
    uint32_t dstB = smem_b + (uint32_t)(A_FLOATS + (t >> 6) * BSTR + (t & 63) * 4) * 4; // j: +j*8*BSTR*4

    constexpr int NK = KD / BK;

    // prologue: stages 0..NSTG-2
    #pragma unroll
    for (int p = 0; p < NSTG - 1; p++) {
        uint32_t so = (uint32_t)p * STAGE_BYTES;
        int k0 = p * BK;
        CP_ASYNC16(dstA + so, srcA + k0);
        CP_ASYNC16(dstA + 64 * KSTR * 4 + so, srcA + (size_t)64 * KD + k0);
        #pragma unroll
        for (int j = 0; j < 4; j++)
            CP_ASYNC16(dstB + j * 8 * BSTR * 4 + so, srcB + (size_t)(k0 + j * 8) * ND);
        CP_COMMIT();
    }

    float acc[4][4][4];
    #pragma unroll
    for (int mi = 0; mi < 4; mi++)
        #pragma unroll
        for (int ni = 0; ni < 4; ni++)
            #pragma unroll
            for (int r = 0; r < 4; r++) acc[mi][ni][r] = 0.f;

    for (int i = 0; i < NK; i++) {
        CP_WAIT(NSTG - 2);
        __syncthreads();
        // prefetch stage i+NSTG-1 (commit unconditionally: keeps group ledger aligned)
        if (i + NSTG - 1 < NK) {
            uint32_t so = (uint32_t)((i + NSTG - 1) % NSTG) * STAGE_BYTES;
            int k0 = (i + NSTG - 1) * BK;
            CP_ASYNC16(dstA + so, srcA + k0);
            CP_ASYNC16(dstA + 64 * KSTR * 4 + so, srcA + (size_t)64 * KD + k0);
            #pragma unroll
            for (int j = 0; j < 4; j++)
                CP_ASYNC16(dstB + j * 8 * BSTR * 4 + so, srcB + (size_t)(k0 + j * 8) * ND);
        }
        CP_COMMIT();
        // compute stage i
        const float* Asf = smem + (i % NSTG) * STAGE_FLOATS;
        const float* Bsf = Asf + A_FLOATS;
        const uint32_t* As = (const uint32_t*)Asf;
        #pragma unroll
        for (int kk = 0; kk < 4; kk++) {
            int k = kk * 8;
            uint32_t a[4][4];
            #pragma unroll
            for (int mi = 0; mi < 4; mi++) {
                int rb = wm * 64 + mi * 16;
                a[mi][0] = As[(rb + qr) * KSTR + k + qc];
                a[mi][1] = As[(rb + 8 + qr) * KSTR + k + qc];
                a[mi][2] = As[(rb + qr) * KSTR + k + 4 + qc];
                a[mi][3] = As[(rb + 8 + qr) * KSTR + k + 4 + qc];
            }
            uint32_t b[4][2];
            #pragma unroll
            for (int ni = 0; ni < 4; ni++) {
                int nbr = wn * 32 + ni * 8 + qr;
                b[ni][0] = __float_as_uint(rn_tf32(Bsf[(k + qc) * BSTR + nbr]));
                b[ni][1] = __float_as_uint(rn_tf32(Bsf[(k + 4 + qc) * BSTR + nbr]));
            }
            #pragma unroll
            for (int mi = 0; mi < 4; mi++)
                #pragma unroll
                for (int ni = 0; ni < 4; ni++)
                    mma_tf32(acc[mi][ni][0], acc[mi][ni][1], acc[mi][ni][2], acc[mi][ni][3],
                             a[mi][0], a[mi][1], a[mi][2], a[mi][3],
                             b[ni][0], b[ni][1]);
        }
    }

    __syncthreads();

    // epilogue: bias (+relu +tf32-round for FIRST), direct global stores
    #pragma unroll
    for (int mi = 0; mi < 4; mi++) {
        int row0 = wm * 64 + mi * 16 + qr;
        float* o0 = Omat + (m0 + row0) * ND + n0;
        float* o1 = o0 + (size_t)8 * ND;
        #pragma unroll
        for (int ni = 0; ni < 4; ni++) {
            int col = wn * 32 + ni * 8 + qc * 2;
            float bx = biasb[col], by = biasb[col + 1];
            float2 v0, v1;
            v0.x = acc[mi][ni][0] + bx;  v0.y = acc[mi][ni][1] + by;
            v1.x = acc[mi][ni][2] + bx;  v1.y = acc[mi][ni][3] + by;
            if (FIRST) {
                v0.x = rn_tf32(fmaxf(v0.x, 0.f));  v0.y = rn_tf32(fmaxf(v0.y, 0.f));
                v1.x = rn_tf32(fmaxf(v1.x, 0.f));  v1.y = rn_tf32(fmaxf(v1.y, 0.f));
            }
            *(float2*)(o0 + col) = v0;
            *(float2*)(o1 + col) = v1;
        }
    }
}

// ---------------- sampled FFMA verification of the mma output ----------------
template<int KD, int ND, bool FIRST>
__global__ __launch_bounds__(256) void check_kernel(const float* __restrict__ W,
                                                    const float* __restrict__ bias_all) {
    int t = threadIdx.x;
    int nrows = g_po[NE];
    int r = (t & 15) * (nrows >> 4);
    if (r >= nrows) r = nrows - 1;
    int col = (t >> 4) * (ND / 16);
    int e = g_tile_e[r >> 7];
    const float* a = (FIRST ? g_xg : g_h) + (size_t)r * KD;
    const float* w = W + (size_t)e * KD * ND + col;
    float s = 0.f;
    for (int k = 0; k < KD; k++) s += a[k] * rn_tf32(w[(size_t)k * ND]);
    s += bias_all[(size_t)e * ND + col];
    if (FIRST) s = fmaxf(s, 0.f);
    float got = (FIRST ? g_h : g_y)[(size_t)r * ND + col];
    if (fabsf(got - s) > 0.02f * (fabsf(s) + 0.05f))
        atomicExch(FIRST ? &g_bad1 : &g_bad2, 1);
}

// ---------------- FFMA repair GEMM (safety net; runs only if check fails) ----------------
template<int KD, int ND, bool FIRST>
__global__ __launch_bounds__(256) void repair_gemm(const float* __restrict__ W,
                                                   const float* __restrict__ bias_all) {
    int bad = FIRST ? g_bad1 : (g_bad1 | g_bad2);
    if (!bad) return;
    int tile = blockIdx.y;
    if (tile >= g_ntiles) return;
    const float* Amat = FIRST ? g_xg : g_h;
    float*       Omat = FIRST ? g_h  : g_y;
    int e  = g_tile_e[tile];
    int n0 = blockIdx.x * 128;
    size_t m0 = (size_t)tile * 128;
    const float* Ab = Amat + m0 * KD;
    const float* Bk = W + (size_t)e * KD * ND + n0;     // [k][n]
    const float* biasb = bias_all + (size_t)e * ND + n0;

    __shared__ float As[16][128];
    __shared__ float Bs[16][128];

    int t = threadIdx.x;
    int rr = t >> 1;
    int kc = (t & 1) * 8;
    int bk = t >> 4;
    int bn = (t & 15) * 8;
    int tx = t & 15, ty = t >> 4;

    float acc[8][8];
    #pragma unroll
    for (int i = 0; i < 8; i++)
        #pragma unroll
        for (int j = 0; j < 8; j++) acc[i][j] = 0.f;

    for (int k0 = 0; k0 < KD; k0 += 16) {
        float4 a0 = *(const float4*)(Ab + (size_t)rr * KD + k0 + kc);
        float4 a1 = *(const float4*)(Ab + (size_t)rr * KD + k0 + kc + 4);
        const float* bp = Bk + (size_t)(k0 + bk) * ND + bn;
        float4 b0 = *(const float4*)(bp);
        float4 b1 = *(const float4*)(bp + 4);
        __syncthreads();
        As[kc + 0][rr] = a0.x; As[kc + 1][rr] = a0.y;
        As[kc + 2][rr] = a0.z; As[kc + 3][rr] = a0.w;
        As[kc + 4][rr] = a1.x; As[kc + 5][rr] = a1.y;
        As[kc + 6][rr] = a1.z; As[kc + 7][rr] = a1.w;
        *(float4*)&Bs[bk][bn]     = b0;
        *(float4*)&Bs[bk][bn + 4] = b1;
        __syncthreads();
        #pragma unroll
        for (int kk = 0; kk < 16; kk++) {
            float a[8], b[8];
            *(float4*)&a[0] = *(float4*)&As[kk][ty * 8];
            *(float4*)&a[4] = *(float4*)&As[kk][ty * 8 + 4];
            *(float4*)&b[0] = *(float4*)&Bs[kk][tx * 8];
            *(float4*)&b[4] = *(float4*)&Bs[kk][tx * 8 + 4];
            #pragma unroll
            for (int i = 0; i < 8; i++)
                #pragma unroll
                for (int j = 0; j < 8; j++) acc[i][j] += a[i] * b[j];
        }
    }
    #pragma unroll
    for (int i = 0; i < 8; i++) {
        float* op = Omat + (m0 + ty * 8 + i) * ND + n0 + tx * 8;
        #pragma unroll
        for (int j = 0; j < 8; j += 4) {
            float4 v;
            v.x = acc[i][j + 0] + biasb[tx * 8 + j + 0];
            v.y = acc[i][j + 1] + biasb[tx * 8 + j + 1];
            v.z = acc[i][j + 2] + biasb[tx * 8 + j + 2];
            v.w = acc[i][j + 3] + biasb[tx * 8 + j + 3];
            if (FIRST) {
                v.x = fmaxf(v.x, 0.f); v.y = fmaxf(v.y, 0.f);
                v.z = fmaxf(v.z, 0.f); v.w = fmaxf(v.w, 0.f);
            }
            *(float4*)(op + j) = v;
        }
    }
}

// ---------------- combine ----------------
__global__ __launch_bounds__(256) void combine_kernel(float* __restrict__ out) {
    int i = blockIdx.x * blockDim.x + threadIdx.x;
    if (i >= NTOK * (HID / 4)) return;
    int tkn = i / (HID / 4);
    int c   = (i % (HID / 4)) * 4;
    int p0 = g_prow[tkn * 2], p1 = g_prow[tkn * 2 + 1];
    float w0 = g_topk_w[tkn * 2], w1 = g_topk_w[tkn * 2 + 1];
    float4 a = *(const float4*)(g_y + (size_t)p0 * HID + c);
    float4 b = *(const float4*)(g_y + (size_t)p1 * HID + c);
    float4 v;
    v.x = w0 * a.x + w1 * b.x;
    v.y = w0 * a.y + w1 * b.y;
    v.z = w0 * a.z + w1 * b.z;
    v.w = w0 * a.w + w1 * b.w;
    *(float4*)(out + (size_t)tkn * HID + c) = v;
}

// ---------------- launch ----------------
extern "C" void kernel_launch(void* const* d_in, const int* in_sizes, int n_in,
                              void* d_out, int out_size) {
    const float* x  = (const float*)d_in[0];
    const float* Wg = (const float*)d_in[1];
    const float* bg = (const float*)d_in[2];
    const float* W1 = (const float*)d_in[3];
    const float* b1 = (const float*)d_in[4];
    const float* W2 = (const float*)d_in[5];
    const float* b2 = (const float*)d_in[6];
    float* out = (float*)d_out;

    cudaFuncSetAttribute(mma_gemm<HID, FFN, true>,
                         cudaFuncAttributeMaxDynamicSharedMemorySize, MM_SMEM);
    cudaFuncSetAttribute(mma_gemm<FFN, HID, false>,
                         cudaFuncAttributeMaxDynamicSharedMemorySize, MM_SMEM);

    zero_kernel<<<1, 256>>>();
    gate_kernel<<<(NTOK * 32) / 256, 256>>>(x, Wg, bg);
    scanpad_kernel<<<1, 256>>>();
    assign_kernel<<<NTOK / 256, 256>>>();
    gather_kernel<<<NROWSP, 256>>>(x);

    mma_gemm<HID, FFN, true><<<dim3(FFN / 256, MAXTILES), 512, MM_SMEM>>>(W1, b1);
    check_kernel<HID, FFN, true><<<1, 256>>>(W1, b1);
    repair_gemm<HID, FFN, true><<<dim3(FFN / 128, MAXTILES), 256>>>(W1, b1);

    mma_gemm<FFN, HID, false><<<dim3(HID / 256, MAXTILES), 512, MM_SMEM>>>(W2, b2);
    check_kernel<FFN, HID, false><<<1, 256>>>(W2, b2);
    repair_gemm<FFN, HID, false><<<dim3(HID / 128, MAXTILES), 256>>>(W2, b2);

    combine_kernel<<<(NTOK * (HID / 4)) / 256, 256>>>(out);
}

// round 11
// speedup vs baseline: 1.6145x; 1.6145x over previous
#include <cuda_runtime.h>
#include <cuda_bf16.h>
#include <math.h>
#include <stdint.h>

#define NTOK 16384
#define HID  1024
#define FFN  4096
#define NE   8
#define NROWS (NTOK * 2)
#define NROWSP (NROWS + NE * 128)     // padded rows upper bound = 33792
#define MAXTILES (NROWSP / 128)       // 264

// ---------------- device scratch ----------------
__device__ int   g_cnt[NE];
__device__ int   g_cur[NE];
__device__ int   g_po[NE + 1];
__device__ int   g_ntiles;
__device__ int   g_bad1;
__device__ int   g_bad2;
__device__ int   g_tile_e[MAXTILES];
__device__ int   g_topk_e[NROWS];
__device__ float g_topk_w[NROWS];
__device__ int   g_rowtok[NROWSP];
__device__ int   g_prow[NROWS];
__device__ float g_xg[(size_t)NROWSP * HID];      // permuted k-groups
__device__ float g_h[(size_t)NROWSP * FFN];       // permuted k-groups
__device__ float g_y[(size_t)NROWSP * HID];       // natural
__device__ float g_w1t[(size_t)NE * FFN * HID];   // [e][n][k] permuted k, tf32-rounded
__device__ float g_w2t[(size_t)NE * HID * FFN];   // [e][n][k] permuted k, tf32-rounded

// perm within each 8-float k-group: value k_j stored at 2*(j&3)+(j>>2)
__device__ __forceinline__ int perm8(int j) { return ((j & 3) << 1) | (j >> 2); }

// ---------------- helpers ----------------
__device__ __forceinline__ float rn_tf32(float v) {
    float o;
    asm("cvt.rna.tf32.f32 %0, %1;" : "=f"(o) : "f"(v));
    return o;
}

#define CP_ASYNC16(dst, src) \
    asm volatile("cp.async.cg.shared.global [%0], [%1], 16;" :: "r"(dst), "l"(src))
#define CP_COMMIT() asm volatile("cp.async.commit_group;" ::: "memory")
#define CP_WAIT(n)  asm volatile("cp.async.wait_group %0;" :: "n"(n) : "memory")

__device__ __forceinline__ void mma_tf32(float& c0, float& c1, float& c2, float& c3,
                                         uint32_t a0, uint32_t a1, uint32_t a2, uint32_t a3,
                                         uint32_t b0, uint32_t b1) {
    asm volatile(
        "mma.sync.aligned.m16n8k8.row.col.f32.tf32.tf32.f32 "
        "{%0,%1,%2,%3}, {%4,%5,%6,%7}, {%8,%9}, {%0,%1,%2,%3};"
        : "+f"(c0), "+f"(c1), "+f"(c2), "+f"(c3)
        : "r"(a0), "r"(a1), "r"(a2), "r"(a3), "r"(b0), "r"(b1));
}

// ---------------- gating ----------------
__global__ __launch_bounds__(256) void zero_kernel() {
    int t = threadIdx.x;
    if (t < NE) { g_cnt[t] = 0; g_cur[t] = 0; }
    if (t == 8) g_bad1 = 0;
    if (t == 9) g_bad2 = 0;
}

__global__ __launch_bounds__(256) void gate_kernel(const float* __restrict__ x,
                                                   const float* __restrict__ Wg,
                                                   const float* __restrict__ bg) {
    int warp = (blockIdx.x * blockDim.x + threadIdx.x) >> 5;
    int lane = threadIdx.x & 31;
    if (warp >= NTOK) return;
    const float* xr = x + (size_t)warp * HID;
    float acc[NE];
    #pragma unroll
    for (int e = 0; e < NE; e++) acc[e] = 0.f;
    for (int i = lane; i < HID; i += 32) {
        float xi = xr[i];
        #pragma unroll
        for (int e = 0; e < NE; e++) acc[e] += xi * Wg[i * NE + e];
    }
    #pragma unroll
    for (int o = 16; o; o >>= 1) {
        #pragma unroll
        for (int e = 0; e < NE; e++) acc[e] += __shfl_xor_sync(0xFFFFFFFFu, acc[e], o);
    }
    if (lane == 0) {
        float s[NE];
        #pragma unroll
        for (int e = 0; e < NE; e++) s[e] = acc[e] + bg[e];
        int i0 = 0;
        #pragma unroll
        for (int e = 1; e < NE; e++) if (s[e] > s[i0]) i0 = e;
        int i1 = -1;
        #pragma unroll
        for (int e = 0; e < NE; e++) {
            if (e == i0) continue;
            if (i1 < 0 || s[e] > s[i1]) i1 = e;
        }
        float e1 = expf(s[i1] - s[i0]);
        float denom = 1.f + e1;
        g_topk_e[warp * 2]     = i0;  g_topk_w[warp * 2]     = 1.f / denom;
        g_topk_e[warp * 2 + 1] = i1;  g_topk_w[warp * 2 + 1] = e1 / denom;
        atomicAdd(&g_cnt[i0], 1);
        atomicAdd(&g_cnt[i1], 1);
    }
}

// scan + pad-fill in one block
__global__ __launch_bounds__(256) void scanpad_kernel() {
    if (threadIdx.x == 0) {
        int acc = 0, t = 0;
        for (int e = 0; e < NE; e++) {
            g_po[e] = acc;
            int nt = (g_cnt[e] + 127) >> 7;
            for (int i = 0; i < nt; i++) g_tile_e[t++] = e;
            acc += nt << 7;
        }
        g_po[NE] = acc;
        g_ntiles = t;
    }
    __syncthreads();
    for (int e = 0; e < NE; e++) {
        int base = g_po[e];
        int padded = g_po[e + 1] - base;
        for (int r = g_cnt[e] + threadIdx.x; r < padded; r += 256)
            g_rowtok[base + r] = 0;
    }
}

__global__ __launch_bounds__(256) void assign_kernel() {
    int t = blockIdx.x * blockDim.x + threadIdx.x;
    if (t >= NTOK) return;
    #pragma unroll
    for (int k = 0; k < 2; k++) {
        int e = g_topk_e[t * 2 + k];
        int p = g_po[e] + atomicAdd(&g_cur[e], 1);
        g_rowtok[p] = t;
        g_prow[t * 2 + k] = p;
    }
}

// gather x rows into padded g_xg: tf32-rounded, 8-group permuted
__global__ __launch_bounds__(128) void gather_kernel(const float* __restrict__ x) {
    int row = blockIdx.x;
    if (row >= g_po[NE]) return;
    int tok = g_rowtok[row];
    const float4* s = (const float4*)(x + (size_t)tok * HID);
    float4* d = (float4*)(g_xg + (size_t)row * HID);
    int g = threadIdx.x;                    // 8-float group
    float4 lo = s[2 * g], hi = s[2 * g + 1];
    float4 o0, o1;                          // [k0,k4,k1,k5], [k2,k6,k3,k7]
    o0.x = rn_tf32(lo.x); o0.y = rn_tf32(hi.x); o0.z = rn_tf32(lo.y); o0.w = rn_tf32(hi.y);
    o1.x = rn_tf32(lo.z); o1.y = rn_tf32(hi.z); o1.z = rn_tf32(lo.w); o1.w = rn_tf32(hi.w);
    d[2 * g] = o0; d[2 * g + 1] = o1;
}

// transpose W [e][k][n] -> g_w1t/g_w2t [e][n][perm k], tf32-rounded (device-side dst!)
template<bool TOW1>
__global__ __launch_bounds__(256) void transpose_kernel(const float* __restrict__ src) {
    constexpr int R = TOW1 ? HID : FFN;    // k dim
    constexpr int C = TOW1 ? FFN : HID;    // n dim
    float* __restrict__ dstbase = TOW1 ? g_w1t : g_w2t;
    __shared__ float t[32][33];
    int e = blockIdx.z;
    int c0 = blockIdx.x * 32, r0 = blockIdx.y * 32;
    const float* s = src + (size_t)e * R * C;
    float* d = dstbase + (size_t)e * R * C;
    int tx = threadIdx.x & 31, ty = threadIdx.x >> 5;
    #pragma unroll
    for (int i = 0; i < 32; i += 8)
        t[ty + i][tx] = rn_tf32(s[(size_t)(r0 + ty + i) * C + c0 + tx]);
    __syncthreads();
    int kp = r0 + (tx & ~7) + perm8(tx & 7);
    #pragma unroll
    for (int i = 0; i < 32; i += 8)
        d[(size_t)(c0 + ty + i) * R + kp] = t[tx][ty + i];
}

// ---------------- tf32 mma GEMM: 128x256x32, 8 warps, paired LDS.64 fragments --------
#define BK 32
#define KSTR 40
#define A_FLOATS (128 * KSTR)              // 5120
#define B_FLOATS (256 * KSTR)              // 10240
#define STAGE_FLOATS (A_FLOATS + B_FLOATS) // 15360
#define STAGE_BYTES (STAGE_FLOATS * 4)     // 61440
#define NSTG 3
#define MM_SMEM (NSTG * STAGE_BYTES)       // 184320

template<int KD, int ND, bool FIRST>
__global__ __launch_bounds__(256, 1) void mma_gemm(const float* __restrict__ bias_all) {
    int tile = blockIdx.y;
    if (tile >= g_ntiles) return;
    const float* Amat = FIRST ? g_xg  : g_h;
    const float* Wt   = FIRST ? g_w1t : g_w2t;
    float*       Omat = FIRST ? g_h   : g_y;
    int e  = g_tile_e[tile];
    int n0 = blockIdx.x * 256;
    size_t m0 = (size_t)tile * 128;
    const float* Ab = Amat + m0 * KD;
    const float* Bb = Wt + ((size_t)e * ND + n0) * KD;   // [n][k] permuted rows
    const float* biasb = bias_all + (size_t)e * ND + n0;

    extern __shared__ float smem[];
    uint32_t smem_b = (uint32_t)__cvta_generic_to_shared(smem);

    int t = threadIdx.x;
    int wid = t >> 5, lane = t & 31;
    int wm = wid & 1, wn = wid >> 1;        // warp tile (wm*64 rows, wn*64 cols)
    int qr = lane >> 2, qc = lane & 3;

    // async-copy slots: A = 4 chunks/thread, B = 8 chunks/thread
    const float* srcA[4]; uint32_t dstA[4];
    #pragma unroll
    for (int j = 0; j < 4; j++) {
        int u = t + 256 * j;
        int m = u >> 3, c = u & 7;
        srcA[j] = Ab + (size_t)m * KD + c * 4;
        dstA[j] = smem_b + (uint32_t)(m * KSTR + c * 4) * 4;
    }
    const float* srcB[8]; uint32_t dstB[8];
    #pragma unroll
    for (int j = 0; j < 8; j++) {
        int u = t + 256 * j;
        int n = u >> 3, c = u & 7;
        srcB[j] = Bb + (size_t)n * KD + c * 4;
        dstB[j] = smem_b + (uint32_t)(A_FLOATS + n * KSTR + c * 4) * 4;
    }

    constexpr int NK = KD / BK;

    #pragma unroll
    for (int p = 0; p < NSTG - 1; p++) {
        uint32_t so = (uint32_t)p * STAGE_BYTES;
        int k0 = p * BK;
        #pragma unroll
        for (int j = 0; j < 4; j++) CP_ASYNC16(dstA[j] + so, srcA[j] + k0);
        #pragma unroll
        for (int j = 0; j < 8; j++) CP_ASYNC16(dstB[j] + so, srcB[j] + k0);
        CP_COMMIT();
    }

    float acc[4][8][4];
    #pragma unroll
    for (int mi = 0; mi < 4; mi++)
        #pragma unroll
        for (int ni = 0; ni < 8; ni++)
            #pragma unroll
            for (int r = 0; r < 4; r++) acc[mi][ni][r] = 0.f;

    for (int i = 0; i < NK; i++) {
        CP_WAIT(NSTG - 2);
        __syncthreads();
        if (i + NSTG - 1 < NK) {
            uint32_t so = (uint32_t)((i + NSTG - 1) % NSTG) * STAGE_BYTES;
            int k0 = (i + NSTG - 1) * BK;
            #pragma unroll
            for (int j = 0; j < 4; j++) CP_ASYNC16(dstA[j] + so, srcA[j] + k0);
            #pragma unroll
            for (int j = 0; j < 8; j++) CP_ASYNC16(dstB[j] + so, srcB[j] + k0);
        }
        CP_COMMIT();
        // compute stage i: all fragment loads are paired LDS.64 off two bases
        const float* Asf = smem + (i % NSTG) * STAGE_FLOATS;
        const float* aB = Asf + (wm * 64 + qr) * KSTR + 2 * qc;
        const float* bB = Asf + A_FLOATS + (wn * 64 + qr) * KSTR + 2 * qc;
        #pragma unroll
        for (int kk = 0; kk < 4; kk++) {
            int k = kk * 8;
            uint32_t a[4][4];
            #pragma unroll
            for (int mi = 0; mi < 4; mi++) {
                float2 a02 = *(const float2*)(aB + mi * 16 * KSTR + k);
                float2 a13 = *(const float2*)(aB + (mi * 16 + 8) * KSTR + k);
                a[mi][0] = __float_as_uint(a02.x);
                a[mi][2] = __float_as_uint(a02.y);
                a[mi][1] = __float_as_uint(a13.x);
                a[mi][3] = __float_as_uint(a13.y);
            }
            uint32_t b[8][2];
            #pragma unroll
            for (int ni = 0; ni < 8; ni++) {
                float2 b01 = *(const float2*)(bB + ni * 8 * KSTR + k);
                b[ni][0] = __float_as_uint(b01.x);
                b[ni][1] = __float_as_uint(b01.y);
            }
            #pragma unroll
            for (int mi = 0; mi < 4; mi++)
                #pragma unroll
                for (int ni = 0; ni < 8; ni++)
                    mma_tf32(acc[mi][ni][0], acc[mi][ni][1], acc[mi][ni][2], acc[mi][ni][3],
                             a[mi][0], a[mi][1], a[mi][2], a[mi][3],
                             b[ni][0], b[ni][1]);
        }
    }

    __syncthreads();

    // epilogue. FIRST: permuted scattered stores (h is a K-operand downstream).
    int p0 = perm8(2 * qc), p1 = perm8(2 * qc + 1);
    #pragma unroll
    for (int mi = 0; mi < 4; mi++) {
        int row0 = wm * 64 + mi * 16 + qr;
        float* o0 = Omat + (m0 + row0) * ND + n0;
        float* o1 = o0 + (size_t)8 * ND;
        #pragma unroll
        for (int ni = 0; ni < 8; ni++) {
            int cb = wn * 64 + ni * 8;
            float bx = biasb[cb + 2 * qc], by = biasb[cb + 2 * qc + 1];
            float e0 = acc[mi][ni][0] + bx, e1 = acc[mi][ni][1] + by;
            float e2 = acc[mi][ni][2] + bx, e3 = acc[mi][ni][3] + by;
            if (FIRST) {
                o0[cb + p0] = rn_tf32(fmaxf(e0, 0.f));
                o0[cb + p1] = rn_tf32(fmaxf(e1, 0.f));
                o1[cb + p0] = rn_tf32(fmaxf(e2, 0.f));
                o1[cb + p1] = rn_tf32(fmaxf(e3, 0.f));
            } else {
                float2 v0 = {e0, e1}, v1 = {e2, e3};
                *(float2*)(o0 + cb + 2 * qc) = v0;
                *(float2*)(o1 + cb + 2 * qc) = v1;
            }
        }
    }
}

// ---------------- sampled FFMA verification (permuted layouts stay aligned) ----------
template<int KD, int ND, bool FIRST>
__global__ __launch_bounds__(256) void check_kernel(const float* __restrict__ bias_all) {
    int t = threadIdx.x;
    int nrows = g_po[NE];
    int r = (t & 15) * (nrows >> 4);
    if (r >= nrows) r = nrows - 1;
    int col = (t >> 4) * (ND / 16);          // multiple of 8 -> perm-invariant
    int e = g_tile_e[r >> 7];
    const float* a = (FIRST ? g_xg : g_h) + (size_t)r * KD;
    const float* w = (FIRST ? g_w1t : g_w2t) + ((size_t)e * ND + col) * KD;
    float s = 0.f;
    for (int k = 0; k < KD; k++) s += a[k] * w[k];
    s += bias_all[(size_t)e * ND + col];
    if (FIRST) s = fmaxf(s, 0.f);
    float got = (FIRST ? g_h : g_y)[(size_t)r * ND + col];
    if (fabsf(got - s) > 0.02f * (fabsf(s) + 0.05f))
        atomicExch(FIRST ? &g_bad1 : &g_bad2, 1);
}

// ---------------- FFMA repair GEMM (safety net; runs only if check fails) ------------
template<int KD, int ND, bool FIRST>
__global__ __launch_bounds__(256) void repair_gemm(const float* __restrict__ bias_all) {
    int bad = FIRST ? g_bad1 : (g_bad1 | g_bad2);
    if (!bad) return;
    int tile = blockIdx.y;
    if (tile >= g_ntiles) return;
    const float* Amat = FIRST ? g_xg  : g_h;
    const float* Wt   = FIRST ? g_w1t : g_w2t;
    float*       Omat = FIRST ? g_h   : g_y;
    int e  = g_tile_e[tile];
    int n0 = blockIdx.x * 128;
    size_t m0 = (size_t)tile * 128;
    const float* Ab = Amat + m0 * KD;
    const float* Bt = Wt + ((size_t)e * ND + n0) * KD;
    const float* biasb = bias_all + (size_t)e * ND + n0;

    __shared__ float As[16][128];
    __shared__ float Bs[16][128];

    int t = threadIdx.x;
    int rr = t >> 1;
    int kc = (t & 1) * 8;
    int tx = t & 15, ty = t >> 4;

    float acc[8][8];
    #pragma unroll
    for (int i = 0; i < 8; i++)
        #pragma unroll
        for (int j = 0; j < 8; j++) acc[i][j] = 0.f;

    for (int k0 = 0; k0 < KD; k0 += 16) {
        float4 a0 = *(const float4*)(Ab + (size_t)rr * KD + k0 + kc);
        float4 a1 = *(const float4*)(Ab + (size_t)rr * KD + k0 + kc + 4);
        float4 b0 = *(const float4*)(Bt + (size_t)rr * KD + k0 + kc);
        float4 b1 = *(const float4*)(Bt + (size_t)rr * KD + k0 + kc + 4);
        __syncthreads();
        As[kc + 0][rr] = a0.x; As[kc + 1][rr] = a0.y;
        As[kc + 2][rr] = a0.z; As[kc + 3][rr] = a0.w;
        As[kc + 4][rr] = a1.x; As[kc + 5][rr] = a1.y;
        As[kc + 6][rr] = a1.z; As[kc + 7][rr] = a1.w;
        Bs[kc + 0][rr] = b0.x; Bs[kc + 1][rr] = b0.y;
        Bs[kc + 2][rr] = b0.z; Bs[kc + 3][rr] = b0.w;
        Bs[kc + 4][rr] = b1.x; Bs[kc + 5][rr] = b1.y;
        Bs[kc + 6][rr] = b1.z; Bs[kc + 7][rr] = b1.w;
        __syncthreads();
        #pragma unroll
        for (int kk = 0; kk < 16; kk++) {
            float a[8], b[8];
            *(float4*)&a[0] = *(float4*)&As[kk][ty * 8];
            *(float4*)&a[4] = *(float4*)&As[kk][ty * 8 + 4];
            *(float4*)&b[0] = *(float4*)&Bs[kk][tx * 8];
            *(float4*)&b[4] = *(float4*)&Bs[kk][tx * 8 + 4];
            #pragma unroll
            for (int i = 0; i < 8; i++)
                #pragma unroll
                for (int j = 0; j < 8; j++) acc[i][j] += a[i] * b[j];
        }
    }
    #pragma unroll
    for (int i = 0; i < 8; i++) {
        float* op = Omat + (m0 + ty * 8 + i) * ND + n0 + tx * 8;
        #pragma unroll
        for (int j = 0; j < 8; j++) {
            float v = acc[i][j] + biasb[tx * 8 + j];
            if (FIRST) {
                op[perm8(j)] = rn_tf32(fmaxf(v, 0.f));  // h stays permuted downstream
            } else {
                op[j] = v;
            }
        }
    }
}

// ---------------- combine ----------------
__global__ __launch_bounds__(256) void combine_kernel(float* __restrict__ out) {
    int i = blockIdx.x * blockDim.x + threadIdx.x;
    if (i >= NTOK * (HID / 4)) return;
    int tkn = i / (HID / 4);
    int c   = (i % (HID / 4)) * 4;
    int p0 = g_prow[tkn * 2], p1 = g_prow[tkn * 2 + 1];
    float w0 = g_topk_w[tkn * 2], w1 = g_topk_w[tkn * 2 + 1];
    float4 a = *(const float4*)(g_y + (size_t)p0 * HID + c);
    float4 b = *(const float4*)(g_y + (size_t)p1 * HID + c);
    float4 v;
    v.x = w0 * a.x + w1 * b.x;
    v.y = w0 * a.y + w1 * b.y;
    v.z = w0 * a.z + w1 * b.z;
    v.w = w0 * a.w + w1 * b.w;
    *(float4*)(out + (size_t)tkn * HID + c) = v;
}

// ---------------- launch ----------------
extern "C" void kernel_launch(void* const* d_in, const int* in_sizes, int n_in,
                              void* d_out, int out_size) {
    const float* x  = (const float*)d_in[0];
    const float* Wg = (const float*)d_in[1];
    const float* bg = (const float*)d_in[2];
    const float* W1 = (const float*)d_in[3];
    const float* b1 = (const float*)d_in[4];
    const float* W2 = (const float*)d_in[5];
    const float* b2 = (const float*)d_in[6];
    float* out = (float*)d_out;

    cudaFuncSetAttribute(mma_gemm<HID, FFN, true>,
                         cudaFuncAttributeMaxDynamicSharedMemorySize, MM_SMEM);
    cudaFuncSetAttribute(mma_gemm<FFN, HID, false>,
                         cudaFuncAttributeMaxDynamicSharedMemorySize, MM_SMEM);

    zero_kernel<<<1, 256>>>();
    gate_kernel<<<(NTOK * 32) / 256, 256>>>(x, Wg, bg);
    scanpad_kernel<<<1, 256>>>();
    assign_kernel<<<NTOK / 256, 256>>>();
    gather_kernel<<<NROWSP, 128>>>(x);
    transpose_kernel<true ><<<dim3(FFN / 32, HID / 32, NE), 256>>>(W1);
    transpose_kernel<false><<<dim3(HID / 32, FFN / 32, NE), 256>>>(W2);

    mma_gemm<HID, FFN, true><<<dim3(FFN / 256, MAXTILES), 256, MM_SMEM>>>(b1);
    check_kernel<HID, FFN, true><<<1, 256>>>(b1);
    repair_gemm<HID, FFN, true><<<dim3(FFN / 128, MAXTILES), 256>>>(b1);

    mma_gemm<FFN, HID, false><<<dim3(HID / 256, MAXTILES), 256, MM_SMEM>>>(b2);
    check_kernel<FFN, HID, false><<<1, 256>>>(b2);
    repair_gemm<FFN, HID, false><<<dim3(HID / 128, MAXTILES), 256>>>(b2);

    combine_kernel<<<(NTOK * (HID / 4)) / 256, 256>>>(out);
}